// round 8
// baseline (speedup 1.0000x reference)
#include <cuda_runtime.h>
#include <cstdint>

typedef unsigned long long u64;
typedef unsigned int u32;

// ---------------- device scratch (no allocations allowed) ----------------
__device__ float g_part_edge[160][64];
__device__ float g_part_node[160][64];
__device__ float g_zhist[64];
__device__ float g_base[64];
__device__ float g_av[64];
__device__ float g_bv[64];
__device__ float g_w2v[64];

// ---------------- helpers --------------------------------------------------
__device__ __forceinline__ float tanh_ap(float x) {
    float r; asm("tanh.approx.f32 %0,%1;" : "=f"(r) : "f"(x)); return r;
}
__device__ __forceinline__ float sigm(float x) { return 1.f / (1.f + __expf(-x)); }

__device__ __forceinline__ u32 bfpack(float lo, float hi) {
    u32 r; asm("cvt.rn.bf16x2.f32 %0, %1, %2;" : "=r"(r) : "f"(hi), "f"(lo)); return r;
}

__device__ __forceinline__ void mma8(float& d0, float& d1, float& d2, float& d3,
                                     u32 a0, u32 a1, u32 b,
                                     float c0, float c1, float c2, float c3) {
    asm("mma.sync.aligned.m16n8k8.row.col.f32.bf16.bf16.f32 "
        "{%0,%1,%2,%3},{%4,%5},{%6},{%7,%8,%9,%10};"
        : "=f"(d0), "=f"(d1), "=f"(d2), "=f"(d3)
        : "r"(a0), "r"(a1), "r"(b), "f"(c0), "f"(c1), "f"(c2), "f"(c3));
}

#define PNTH  768
#define NW    24              // warps per block
#define CH    128             // rows per warp chunk
#define REDW  68
#define K_PH_SMEM  (61440 + NW * REDW * 4)   // scratch + red

extern __shared__ __align__(16) char dsm_raw[];

// ---------------- per-warp streaming tensor-core MLP reduction ------------
// Plain-float epilogue: per mma, 4 FMNMX + 4 FADD into 16 scalar accs.
// No packed-register asm anywhere.
template<int INF>
__global__ void __launch_bounds__(PNTH) kphase(
    const float* __restrict__ X, const float* __restrict__ W,
    const float* __restrict__ bias, int nrows, float* __restrict__ partials)
{
    const int tid  = threadIdx.x;
    const int lane = tid & 31;
    const int w    = tid >> 5;
    const int gid  = lane >> 2;      // 0..7
    const int tig  = lane & 3;       // 0..3
    float* sw  = (float*)dsm_raw + w * 640;
    float* red = (float*)(dsm_raw + 61440);

    // B fragments (col = nt*8+gid, k = 2tig,2tig+1) + bias C (cols nt*8+2tig..+1)
    u32 bf[8];
    float c0[8], c1[8];
#pragma unroll
    for (int nt = 0; nt < 8; nt++) {
        const int ncol = nt * 8 + gid;
        const float vlo = (2 * tig < INF)     ? W[(2 * tig) * 64 + ncol]     : 0.f;
        const float vhi = (2 * tig + 1 < INF) ? W[(2 * tig + 1) * 64 + ncol] : 0.f;
        bf[nt] = bfpack(vlo, vhi);
        c0[nt] = bias[nt * 8 + 2 * tig];
        c1[nt] = bias[nt * 8 + 2 * tig + 1];
    }
    float acc[16];
#pragma unroll
    for (int i = 0; i < 16; i++) acc[i] = 0.f;

    const int nstreams = gridDim.x * NW;
    const int ws = blockIdx.x * NW + w;
    const int nch = (nrows + CH - 1) / CH;
    const int nelem = nrows * INF;
    constexpr int NV = (CH * INF) / 128;    // float4 per lane per chunk
    float4 pf[NV];

    int c = ws;
    if (c < nch) {
        const int b4 = c * (CH * INF / 4);
        if ((c + 1) * CH <= nrows) {
#pragma unroll
            for (int v = 0; v < NV; v++) pf[v] = ((const float4*)X)[b4 + lane + v * 32];
        } else {
#pragma unroll
            for (int v = 0; v < NV; v++) {
                const int e = (b4 + lane + v * 32) * 4;
                pf[v].x = (e     < nelem) ? X[e]     : 0.f;
                pf[v].y = (e + 1 < nelem) ? X[e + 1] : 0.f;
                pf[v].z = (e + 2 < nelem) ? X[e + 2] : 0.f;
                pf[v].w = (e + 3 < nelem) ? X[e + 3] : 0.f;
            }
        }
    }

    for (; c < nch; c += nstreams) {
#pragma unroll
        for (int v = 0; v < NV; v++) ((float4*)sw)[lane + v * 32] = pf[v];
        __syncwarp();

        const int cn = c + nstreams;
        if (cn < nch) {
            const int b4 = cn * (CH * INF / 4);
            if ((cn + 1) * CH <= nrows) {
#pragma unroll
                for (int v = 0; v < NV; v++) pf[v] = ((const float4*)X)[b4 + lane + v * 32];
            } else {
#pragma unroll
                for (int v = 0; v < NV; v++) {
                    const int e = (b4 + lane + v * 32) * 4;
                    pf[v].x = (e     < nelem) ? X[e]     : 0.f;
                    pf[v].y = (e + 1 < nelem) ? X[e + 1] : 0.f;
                    pf[v].z = (e + 2 < nelem) ? X[e + 2] : 0.f;
                    pf[v].w = (e + 3 < nelem) ? X[e + 3] : 0.f;
                }
            }
        }

        const int rows = min(CH, nrows - c * CH);
        if (rows == CH) {
#pragma unroll
            for (int t = 0; t < 8; t++) {
                const int r0 = t * 16 + gid;
                const float lo0 = (2 * tig < INF)     ? sw[r0 * INF + 2 * tig]           : 0.f;
                const float hi0 = (2 * tig + 1 < INF) ? sw[r0 * INF + 2 * tig + 1]       : 0.f;
                const float lo1 = (2 * tig < INF)     ? sw[(r0 + 8) * INF + 2 * tig]     : 0.f;
                const float hi1 = (2 * tig + 1 < INF) ? sw[(r0 + 8) * INF + 2 * tig + 1] : 0.f;
                const u32 a0 = bfpack(lo0, hi0);
                const u32 a1 = bfpack(lo1, hi1);
#pragma unroll
                for (int nt = 0; nt < 8; nt++) {
                    float d0, d1, d2, d3;
                    mma8(d0, d1, d2, d3, a0, a1, bf[nt], c0[nt], c1[nt], c0[nt], c1[nt]);
                    acc[2 * nt]     += fmaxf(d0, 0.f) + fmaxf(d2, 0.f);
                    acc[2 * nt + 1] += fmaxf(d1, 0.f) + fmaxf(d3, 0.f);
                }
            }
        } else {
#pragma unroll
            for (int t = 0; t < 8; t++) {
                const int r0 = t * 16 + gid;
                const float lo0 = (2 * tig < INF)     ? sw[r0 * INF + 2 * tig]           : 0.f;
                const float hi0 = (2 * tig + 1 < INF) ? sw[r0 * INF + 2 * tig + 1]       : 0.f;
                const float lo1 = (2 * tig < INF)     ? sw[(r0 + 8) * INF + 2 * tig]     : 0.f;
                const float hi1 = (2 * tig + 1 < INF) ? sw[(r0 + 8) * INF + 2 * tig + 1] : 0.f;
                const u32 a0 = bfpack(lo0, hi0);
                const u32 a1 = bfpack(lo1, hi1);
                const float m0 = (r0 < rows) ? 1.f : 0.f;
                const float m1 = (r0 + 8 < rows) ? 1.f : 0.f;
#pragma unroll
                for (int nt = 0; nt < 8; nt++) {
                    float d0, d1, d2, d3;
                    mma8(d0, d1, d2, d3, a0, a1, bf[nt], c0[nt], c1[nt], c0[nt], c1[nt]);
                    acc[2 * nt]     = fmaf(m0, fmaxf(d0, 0.f), acc[2 * nt]);
                    acc[2 * nt]     = fmaf(m1, fmaxf(d2, 0.f), acc[2 * nt]);
                    acc[2 * nt + 1] = fmaf(m0, fmaxf(d1, 0.f), acc[2 * nt + 1]);
                    acc[2 * nt + 1] = fmaf(m1, fmaxf(d3, 0.f), acc[2 * nt + 1]);
                }
            }
        }
        __syncwarp();
    }

    // reduce over gid (shfl xor 4,8,16), then cross-warp via shared
    __syncthreads();
#pragma unroll
    for (int nt = 0; nt < 8; nt++) {
        float lo = acc[2 * nt], hi = acc[2 * nt + 1];
#pragma unroll
        for (int off = 4; off <= 16; off <<= 1) {
            lo += __shfl_xor_sync(0xffffffffu, lo, off);
            hi += __shfl_xor_sync(0xffffffffu, hi, off);
        }
        if (gid == 0) {
            red[w * REDW + nt * 8 + 2 * tig]     = lo;
            red[w * REDW + nt * 8 + 2 * tig + 1] = hi;
        }
    }
    __syncthreads();
    if (tid < 64) {
        float sum = 0.f;
#pragma unroll 8
        for (int r2 = 0; r2 < NW; r2++) sum += red[r2 * REDW + tid];
        partials[blockIdx.x * 64 + tid] = sum;
    }
}

// ---------------- LSTM kernel (1 block, 512 threads) -----------------------
// thread = (j, gate, half): j=tid>>3, gate=(tid>>1)&3, half=tid&1.
// Each thread holds half a gate row (32 scalar weights). Halves combined with
// shfl_xor(1); 4 gates of j gathered in-warp; h double-buffered in shared.
__global__ void __launch_bounds__(512) klstm(
    const float* __restrict__ hist, int T,
    const float* __restrict__ Wih, const float* __restrict__ Whh,
    const float* __restrict__ bih, const float* __restrict__ bhh)
{
    __shared__ float sh_hist[608];
    __shared__ float sh_h[128];

    const int tid = threadIdx.x;
    for (int i = tid; i < T * 3 && i < 608; i += 512) sh_hist[i] = hist[i];
    if (tid < 128) sh_h[tid] = 0.f;
    __syncthreads();

    const int j    = tid >> 3;
    const int gate = (tid >> 1) & 3;
    const int half = tid & 1;
    const int row  = gate * 64 + j;
    const int lane = tid & 31;
    const int base = lane & 24;           // lane of (j, gate=0, half=0)

    float wv[32];
    {
        const float* wr = Whh + row * 64 + half * 32;
#pragma unroll
        for (int k = 0; k < 32; k++) wv[k] = wr[k];
    }
    const float wi0 = Wih[row * 3], wi1 = Wih[row * 3 + 1], wi2 = Wih[row * 3 + 2];
    const float bsum = bih[row] + bhh[row];
    const bool hsh = (T * 3 <= 608);
    const bool is_g = (gate == 2);
    const bool is_owner = ((tid & 7) == 0);
    float c = 0.f;

    for (int t = 0; t < T; t++) {
        const float* xp = hsh ? (sh_hist + t * 3) : (hist + t * 3);
        const float pre = fmaf(wi0, xp[0], fmaf(wi1, xp[1], fmaf(wi2, xp[2], bsum)));
        const float2* hh = (const float2*)(sh_h + (t & 1) * 64 + half * 32);
        float a0 = 0.f, a1 = 0.f, a2 = 0.f, a3 = 0.f;
#pragma unroll
        for (int k = 0; k < 16; k += 4) {
            float2 h0 = hh[k], h1 = hh[k + 1], h2 = hh[k + 2], h3 = hh[k + 3];
            a0 = fmaf(wv[2 * k],     h0.x, a0); a0 = fmaf(wv[2 * k + 1], h0.y, a0);
            a1 = fmaf(wv[2 * k + 2], h1.x, a1); a1 = fmaf(wv[2 * k + 3], h1.y, a1);
            a2 = fmaf(wv[2 * k + 4], h2.x, a2); a2 = fmaf(wv[2 * k + 5], h2.y, a2);
            a3 = fmaf(wv[2 * k + 6], h3.x, a3); a3 = fmaf(wv[2 * k + 7], h3.y, a3);
        }
        float s = (a0 + a1) + (a2 + a3);
        s += __shfl_xor_sync(0xffffffffu, s, 1);
        const float z = pre + s;
        const float a = is_g ? tanh_ap(z) : sigm(z);
        const float gi = __shfl_sync(0xffffffffu, a, base + 0);
        const float gf = __shfl_sync(0xffffffffu, a, base + 2);
        const float gg = __shfl_sync(0xffffffffu, a, base + 4);
        const float go = __shfl_sync(0xffffffffu, a, base + 6);
        if (is_owner) {
            c = fmaf(gf, c, gi * gg);
            sh_h[((t + 1) & 1) * 64 + j] = go * tanh_ap(c);
        }
        __syncthreads();
    }
    if (is_owner) g_zhist[j] = sh_h[(T & 1) * 64 + j];
}

// ---------------- kernel 2: finalize ctx + precompute base/a/b/w2 ---------
__global__ void __launch_bounds__(256) k2(int nb, int Nn, int Ne,
                   const float* __restrict__ W1, const float* __restrict__ b1,
                   const float* __restrict__ W2f)
{
    __shared__ float ctx[192];
    __shared__ float t1[256], t2[256];
    const int tid = threadIdx.x;
    const int c = tid >> 6, j = tid & 63;

    float se = 0.f, sn = 0.f;
    for (int b = c; b < nb; b += 4) {
        se += g_part_edge[b][j];
        sn += g_part_node[b][j];
    }
    t1[tid] = se; t2[tid] = sn;
    __syncthreads();
    if (tid < 64) {
        const float e = t1[tid] + t1[tid + 64] + t1[tid + 128] + t1[tid + 192];
        const float n = t2[tid] + t2[tid + 64] + t2[tid + 128] + t2[tid + 192];
        ctx[tid]       = n * (1.f / (float)Nn);
        ctx[64 + tid]  = e * (1.f / (float)Ne);
        ctx[128 + tid] = g_zhist[tid];
    }
    __syncthreads();
    float p = 0.f;
    const int i0 = c * 48;
#pragma unroll 8
    for (int i = i0; i < i0 + 48; i++) p = fmaf(ctx[i], W1[i * 64 + j], p);
    __syncthreads();
    t1[tid] = p;
    __syncthreads();
    if (tid < 64) {
        g_base[tid] = b1[tid] + ((t1[tid] + t1[tid + 64]) + (t1[tid + 128] + t1[tid + 192]));
        g_av[tid]   = W1[192 * 64 + tid];
        g_bv[tid]   = W1[193 * 64 + tid];
        g_w2v[tid]  = W2f[tid];
    }
}

// ---------------- kernel 3: candidate scoring (scalar, float4 weights) ----
__global__ void __launch_bounds__(256) k3(const int* __restrict__ cand, int P,
                                          const int* __restrict__ Np,
                                          const float* __restrict__ fb2,
                                          float* __restrict__ out)
{
    __shared__ __align__(16) float4 s4f[64];   // {base, av, bv, w2v}[j]
    const int tid = threadIdx.x;
    if (tid < 64)
        s4f[tid] = make_float4(g_base[tid], g_av[tid], g_bv[tid], g_w2v[tid]);
    const float invd = 1.f / ((float)(*Np) - 1.f + 1e-9f);
    const float bias2 = fb2[0];
    __syncthreads();

    const int p0 = blockIdx.x * 1024 + tid;
    float cx[4], cy[4];
#pragma unroll
    for (int i = 0; i < 4; i++) {
        const int p = p0 + i * 256;
        cx[i] = 0.f; cy[i] = 0.f;
        if (p < P) {
            const int2 cp = ((const int2*)cand)[p];
            cx[i] = (float)cp.x * invd;
            cy[i] = (float)cp.y * invd;
        }
    }

    float s[4] = {0.f, 0.f, 0.f, 0.f};
#pragma unroll 8
    for (int j = 0; j < 64; j++) {
        const float4 q = s4f[j];
#pragma unroll
        for (int i = 0; i < 4; i++) {
            float t = fmaf(cx[i], q.y, q.x);
            t = fmaf(cy[i], q.z, t);
            s[i] = fmaf(fmaxf(t, 0.f), q.w, s[i]);
        }
    }
#pragma unroll
    for (int i = 0; i < 4; i++) {
        const int p = p0 + i * 256;
        if (p < P) out[p] = s[i] + bias2;
    }
}

// ---------------- launch ---------------------------------------------------
extern "C" void kernel_launch(void* const* d_in, const int* in_sizes, int n_in,
                              void* d_out, int out_size)
{
    const float* node  = (const float*)d_in[0];
    const float* edge  = (const float*)d_in[1];
    const float* hist  = (const float*)d_in[2];
    const int*   cand  = (const int*)d_in[3];
    const int*   Np    = (const int*)d_in[4];
    const float* nodeW = (const float*)d_in[5];
    const float* nodeb = (const float*)d_in[6];
    const float* edgeW = (const float*)d_in[7];
    const float* edgeb = (const float*)d_in[8];
    const float* Wih   = (const float*)d_in[9];
    const float* Whh   = (const float*)d_in[10];
    const float* bih   = (const float*)d_in[11];
    const float* bhh   = (const float*)d_in[12];
    const float* fW1   = (const float*)d_in[13];
    const float* fb1   = (const float*)d_in[14];
    const float* fW2   = (const float*)d_in[15];
    const float* fb2   = (const float*)d_in[16];

    const int Nn = in_sizes[0] / 2;
    const int Ne = in_sizes[1] / 5;
    const int T  = in_sizes[2] / 3;
    const int P  = in_sizes[3] / 2;

    static bool attr_set = false;
    if (!attr_set) {
        cudaFuncSetAttribute(kphase<2>, cudaFuncAttributeMaxDynamicSharedMemorySize, K_PH_SMEM);
        cudaFuncSetAttribute(kphase<5>, cudaFuncAttributeMaxDynamicSharedMemorySize, K_PH_SMEM);
        attr_set = true;
    }

    float* pn = nullptr; float* pe = nullptr;
    cudaGetSymbolAddress((void**)&pn, g_part_node);
    cudaGetSymbolAddress((void**)&pe, g_part_edge);

    const int GRID = 148;
    klstm<<<1, 512>>>(hist, T, Wih, Whh, bih, bhh);
    kphase<2><<<GRID, PNTH, K_PH_SMEM>>>(node, nodeW, nodeb, Nn, pn);
    kphase<5><<<GRID, PNTH, K_PH_SMEM>>>(edge, edgeW, edgeb, Ne, pe);
    k2<<<1, 256>>>(GRID, Nn, Ne, fW1, fb1, fW2);
    const int g3 = (P + 1023) / 1024;
    k3<<<g3, 256>>>(cand, P, Np, fb2, (float*)d_out);
}

// round 9
// speedup vs baseline: 1.2835x; 1.2835x over previous
#include <cuda_runtime.h>
#include <cstdint>

typedef unsigned long long u64;
typedef unsigned int u32;

// ---------------- device scratch (no allocations allowed) ----------------
__device__ float g_part_edge[160][64];
__device__ float g_part_node[160][64];
__device__ float g_zhist[64];
__device__ float g_base[64];
__device__ float g_av[64];
__device__ float g_bv[64];
__device__ float g_w2v[64];

// ---------------- helpers --------------------------------------------------
__device__ __forceinline__ float tanh_ap(float x) {
    float r; asm("tanh.approx.f32 %0,%1;" : "=f"(r) : "f"(x)); return r;
}
__device__ __forceinline__ float sigm(float x) { return 1.f / (1.f + __expf(-x)); }

__device__ __forceinline__ u32 bfpack(float lo, float hi) {
    u32 r; asm("cvt.rn.bf16x2.f32 %0, %1, %2;" : "=r"(r) : "f"(hi), "f"(lo)); return r;
}

__device__ __forceinline__ void mma8(float& d0, float& d1, float& d2, float& d3,
                                     u32 a0, u32 a1, u32 b,
                                     float c0, float c1, float c2, float c3) {
    asm("mma.sync.aligned.m16n8k8.row.col.f32.bf16.bf16.f32 "
        "{%0,%1,%2,%3},{%4,%5},{%6},{%7,%8,%9,%10};"
        : "=f"(d0), "=f"(d1), "=f"(d2), "=f"(d3)
        : "r"(a0), "r"(a1), "r"(b), "f"(c0), "f"(c1), "f"(c2), "f"(c3));
}

#define NTH   512             // threads per block -> 128-reg budget, NO spills
#define NW    16              // warps per block
#define CH    128             // rows per warp chunk
#define REDW  68

// ---- dynamic shared layout (bytes), union of two uses --------------------
//  phase:  scratch [0, 40960)      16 warps x 640 floats
//          red     [40960, 45312)  16*68 floats
//  LSTM :  hist    [0, 2432)       608 floats
//          shh     [2432, 2944)    2 x 64 floats
#define K1_SMEM 45312

extern __shared__ __align__(16) char dsm_raw[];

// ---------------- per-warp streaming tensor-core MLP reduction ------------
template<int INF>
__device__ __forceinline__ void phase(const float* __restrict__ X,
                                      const float* __restrict__ W,
                                      const float* __restrict__ bias,
                                      int nrows, float* __restrict__ partial,
                                      int nstreams, int ws)
{
    const int tid  = threadIdx.x;
    const int lane = tid & 31;
    const int w    = tid >> 5;
    const int gid  = lane >> 2;      // 0..7
    const int tig  = lane & 3;       // 0..3
    float* sw  = (float*)dsm_raw + w * 640;
    float* red = (float*)(dsm_raw + 40960);

    // B fragments (col = nt*8+gid, k = 2tig,2tig+1) + bias C (cols nt*8+2tig..+1)
    u32 bf[8];
    float c0[8], c1[8];
#pragma unroll
    for (int nt = 0; nt < 8; nt++) {
        const int ncol = nt * 8 + gid;
        const float vlo = (2 * tig < INF)     ? W[(2 * tig) * 64 + ncol]     : 0.f;
        const float vhi = (2 * tig + 1 < INF) ? W[(2 * tig + 1) * 64 + ncol] : 0.f;
        bf[nt] = bfpack(vlo, vhi);
        c0[nt] = bias[nt * 8 + 2 * tig];
        c1[nt] = bias[nt * 8 + 2 * tig + 1];
    }
    float acc[16];
#pragma unroll
    for (int i = 0; i < 16; i++) acc[i] = 0.f;

    const int nch = (nrows + CH - 1) / CH;
    const int nelem = nrows * INF;
    constexpr int NV = (CH * INF) / 128;    // float4 per lane per chunk
    float4 pf[NV];

    __syncthreads();   // protect scratch/red across phases

    int c = ws;
    if (c < nch) {
        const int b4 = c * (CH * INF / 4);
        if ((c + 1) * CH <= nrows) {
#pragma unroll
            for (int v = 0; v < NV; v++) pf[v] = ((const float4*)X)[b4 + lane + v * 32];
        } else {
#pragma unroll
            for (int v = 0; v < NV; v++) {
                const int e = (b4 + lane + v * 32) * 4;
                pf[v].x = (e     < nelem) ? X[e]     : 0.f;
                pf[v].y = (e + 1 < nelem) ? X[e + 1] : 0.f;
                pf[v].z = (e + 2 < nelem) ? X[e + 2] : 0.f;
                pf[v].w = (e + 3 < nelem) ? X[e + 3] : 0.f;
            }
        }
    }

    for (; c < nch; c += nstreams) {
#pragma unroll
        for (int v = 0; v < NV; v++) ((float4*)sw)[lane + v * 32] = pf[v];
        __syncwarp();

        const int cn = c + nstreams;
        if (cn < nch) {
            const int b4 = cn * (CH * INF / 4);
            if ((cn + 1) * CH <= nrows) {
#pragma unroll
                for (int v = 0; v < NV; v++) pf[v] = ((const float4*)X)[b4 + lane + v * 32];
            } else {
#pragma unroll
                for (int v = 0; v < NV; v++) {
                    const int e = (b4 + lane + v * 32) * 4;
                    pf[v].x = (e     < nelem) ? X[e]     : 0.f;
                    pf[v].y = (e + 1 < nelem) ? X[e + 1] : 0.f;
                    pf[v].z = (e + 2 < nelem) ? X[e + 2] : 0.f;
                    pf[v].w = (e + 3 < nelem) ? X[e + 3] : 0.f;
                }
            }
        }

        const int rows = min(CH, nrows - c * CH);
        if (rows == CH) {
#pragma unroll
            for (int t = 0; t < 8; t++) {
                const int r0 = t * 16 + gid;
                const float lo0 = (2 * tig < INF)     ? sw[r0 * INF + 2 * tig]           : 0.f;
                const float hi0 = (2 * tig + 1 < INF) ? sw[r0 * INF + 2 * tig + 1]       : 0.f;
                const float lo1 = (2 * tig < INF)     ? sw[(r0 + 8) * INF + 2 * tig]     : 0.f;
                const float hi1 = (2 * tig + 1 < INF) ? sw[(r0 + 8) * INF + 2 * tig + 1] : 0.f;
                const u32 a0 = bfpack(lo0, hi0);
                const u32 a1 = bfpack(lo1, hi1);
#pragma unroll
                for (int nt = 0; nt < 8; nt++) {
                    float d0, d1, d2, d3;
                    mma8(d0, d1, d2, d3, a0, a1, bf[nt], c0[nt], c1[nt], c0[nt], c1[nt]);
                    acc[2 * nt]     += fmaxf(d0, 0.f) + fmaxf(d2, 0.f);
                    acc[2 * nt + 1] += fmaxf(d1, 0.f) + fmaxf(d3, 0.f);
                }
            }
        } else {
#pragma unroll
            for (int t = 0; t < 8; t++) {
                const int r0 = t * 16 + gid;
                const float lo0 = (2 * tig < INF)     ? sw[r0 * INF + 2 * tig]           : 0.f;
                const float hi0 = (2 * tig + 1 < INF) ? sw[r0 * INF + 2 * tig + 1]       : 0.f;
                const float lo1 = (2 * tig < INF)     ? sw[(r0 + 8) * INF + 2 * tig]     : 0.f;
                const float hi1 = (2 * tig + 1 < INF) ? sw[(r0 + 8) * INF + 2 * tig + 1] : 0.f;
                const u32 a0 = bfpack(lo0, hi0);
                const u32 a1 = bfpack(lo1, hi1);
                const float m0 = (r0 < rows) ? 1.f : 0.f;
                const float m1 = (r0 + 8 < rows) ? 1.f : 0.f;
#pragma unroll
                for (int nt = 0; nt < 8; nt++) {
                    float d0, d1, d2, d3;
                    mma8(d0, d1, d2, d3, a0, a1, bf[nt], c0[nt], c1[nt], c0[nt], c1[nt]);
                    acc[2 * nt]     = fmaf(m0, fmaxf(d0, 0.f), acc[2 * nt]);
                    acc[2 * nt]     = fmaf(m1, fmaxf(d2, 0.f), acc[2 * nt]);
                    acc[2 * nt + 1] = fmaf(m0, fmaxf(d1, 0.f), acc[2 * nt + 1]);
                    acc[2 * nt + 1] = fmaf(m1, fmaxf(d3, 0.f), acc[2 * nt + 1]);
                }
            }
        }
        __syncwarp();
    }

    // reduce over gid (shfl xor 4,8,16), then cross-warp via shared
    __syncthreads();
#pragma unroll
    for (int nt = 0; nt < 8; nt++) {
        float lo = acc[2 * nt], hi = acc[2 * nt + 1];
#pragma unroll
        for (int off = 4; off <= 16; off <<= 1) {
            lo += __shfl_xor_sync(0xffffffffu, lo, off);
            hi += __shfl_xor_sync(0xffffffffu, hi, off);
        }
        if (gid == 0) {
            red[w * REDW + nt * 8 + 2 * tig]     = lo;
            red[w * REDW + nt * 8 + 2 * tig + 1] = hi;
        }
    }
    __syncthreads();
    if (tid < 64) {
        float sum = 0.f;
#pragma unroll 8
        for (int r2 = 0; r2 < NW; r2++) sum += red[r2 * REDW + tid];
        partial[tid] = sum;
    }
}

// ---------------- kernel 1: LSTM (block 0) + node/edge reduce -------------
__global__ void __launch_bounds__(NTH, 1) k1(
    const float* __restrict__ node, const float* __restrict__ edge,
    const float* __restrict__ hist, int Nn, int Ne, int T,
    const float* __restrict__ nodeW, const float* __restrict__ nodeb,
    const float* __restrict__ edgeW, const float* __restrict__ edgeb,
    const float* __restrict__ Wih, const float* __restrict__ Whh,
    const float* __restrict__ bih, const float* __restrict__ bhh)
{
    const int tid = threadIdx.x;

    if (blockIdx.x == 0) {
        // ------- LSTM: 512 threads = (j, gate, half) -----------------------
        float* sh_hist = (float*)dsm_raw;             // 608 floats
        float* sh_h    = (float*)(dsm_raw + 2432);    // 2 x 64 floats

        for (int i = tid; i < T * 3 && i < 608; i += NTH) sh_hist[i] = hist[i];
        if (tid < 128) sh_h[tid] = 0.f;
        __syncthreads();

        const int j    = tid >> 3;
        const int gate = (tid >> 1) & 3;
        const int half = tid & 1;
        const int row  = gate * 64 + j;
        const int lane = tid & 31;
        const int base = lane & 24;

        float wv[32];
        {
            const float* wr = Whh + row * 64 + half * 32;
#pragma unroll
            for (int k = 0; k < 32; k++) wv[k] = wr[k];
        }
        const float wi0 = Wih[row * 3], wi1 = Wih[row * 3 + 1], wi2 = Wih[row * 3 + 2];
        const float bsum = bih[row] + bhh[row];
        const bool hsh = (T * 3 <= 608);
        const bool is_g = (gate == 2);
        const bool is_owner = ((tid & 7) == 0);
        float c = 0.f;

        for (int t = 0; t < T; t++) {
            const float* xp = hsh ? (sh_hist + t * 3) : (hist + t * 3);
            const float pre = fmaf(wi0, xp[0], fmaf(wi1, xp[1], fmaf(wi2, xp[2], bsum)));
            const float2* hh = (const float2*)(sh_h + (t & 1) * 64 + half * 32);
            float a0 = 0.f, a1 = 0.f, a2 = 0.f, a3 = 0.f;
#pragma unroll
            for (int k = 0; k < 16; k += 4) {
                float2 h0 = hh[k], h1 = hh[k + 1], h2 = hh[k + 2], h3 = hh[k + 3];
                a0 = fmaf(wv[2 * k],     h0.x, a0); a0 = fmaf(wv[2 * k + 1], h0.y, a0);
                a1 = fmaf(wv[2 * k + 2], h1.x, a1); a1 = fmaf(wv[2 * k + 3], h1.y, a1);
                a2 = fmaf(wv[2 * k + 4], h2.x, a2); a2 = fmaf(wv[2 * k + 5], h2.y, a2);
                a3 = fmaf(wv[2 * k + 6], h3.x, a3); a3 = fmaf(wv[2 * k + 7], h3.y, a3);
            }
            float s = (a0 + a1) + (a2 + a3);
            s += __shfl_xor_sync(0xffffffffu, s, 1);
            const float z = pre + s;
            const float a = is_g ? tanh_ap(z) : sigm(z);
            const float gi = __shfl_sync(0xffffffffu, a, base + 0);
            const float gf = __shfl_sync(0xffffffffu, a, base + 2);
            const float gg = __shfl_sync(0xffffffffu, a, base + 4);
            const float go = __shfl_sync(0xffffffffu, a, base + 6);
            if (is_owner) {
                c = fmaf(gf, c, gi * gg);
                sh_h[((t + 1) & 1) * 64 + j] = go * tanh_ap(c);
            }
            __syncthreads();
        }
        if (is_owner) g_zhist[j] = sh_h[(T & 1) * 64 + j];
    } else {
        const int nstreams = (gridDim.x - 1) * NW;
        const int ws = (blockIdx.x - 1) * NW + (tid >> 5);
        phase<2>(node, nodeW, nodeb, Nn, g_part_node[blockIdx.x - 1], nstreams, ws);
        phase<5>(edge, edgeW, edgeb, Ne, g_part_edge[blockIdx.x - 1], nstreams, ws);
    }
}

// ---------------- kernel 2: finalize ctx + precompute base/a/b/w2 ---------
__global__ void __launch_bounds__(512) k2(int nb, int Nn, int Ne,
                   const float* __restrict__ W1, const float* __restrict__ b1,
                   const float* __restrict__ W2f)
{
    __shared__ float ctx[192];
    __shared__ float t1[512], t2[512];
    const int tid = threadIdx.x;
    const int c = tid >> 6, j = tid & 63;   // 8 groups

    float se = 0.f, sn = 0.f;
#pragma unroll 4
    for (int b = c; b < nb; b += 8) {
        se += g_part_edge[b][j];
        sn += g_part_node[b][j];
    }
    t1[tid] = se; t2[tid] = sn;
    __syncthreads();
    if (tid < 64) {
        float e = 0.f, n = 0.f;
#pragma unroll
        for (int g = 0; g < 8; g++) { e += t1[g * 64 + tid]; n += t2[g * 64 + tid]; }
        ctx[tid]       = n * (1.f / (float)Nn);
        ctx[64 + tid]  = e * (1.f / (float)Ne);
        ctx[128 + tid] = g_zhist[tid];
    }
    __syncthreads();
    float p = 0.f;
    const int i0 = c * 24;
#pragma unroll 8
    for (int i = i0; i < i0 + 24; i++) p = fmaf(ctx[i], W1[i * 64 + j], p);
    __syncthreads();
    t1[tid] = p;
    __syncthreads();
    if (tid < 64) {
        float s = b1[tid];
#pragma unroll
        for (int g = 0; g < 8; g++) s += t1[g * 64 + tid];
        g_base[tid] = s;
        g_av[tid]   = W1[192 * 64 + tid];
        g_bv[tid]   = W1[193 * 64 + tid];
        g_w2v[tid]  = W2f[tid];
    }
}

// ---------------- kernel 3: candidate scoring (scalar, float4 weights) ----
__global__ void __launch_bounds__(256) k3(const int* __restrict__ cand, int P,
                                          const int* __restrict__ Np,
                                          const float* __restrict__ fb2,
                                          float* __restrict__ out)
{
    __shared__ __align__(16) float4 s4f[64];   // {base, av, bv, w2v}[j]
    const int tid = threadIdx.x;
    if (tid < 64)
        s4f[tid] = make_float4(g_base[tid], g_av[tid], g_bv[tid], g_w2v[tid]);
    const float invd = 1.f / ((float)(*Np) - 1.f + 1e-9f);
    const float bias2 = fb2[0];
    __syncthreads();

    const int p0 = blockIdx.x * 1024 + tid;
    float cx[4], cy[4];
#pragma unroll
    for (int i = 0; i < 4; i++) {
        const int p = p0 + i * 256;
        cx[i] = 0.f; cy[i] = 0.f;
        if (p < P) {
            const int2 cp = ((const int2*)cand)[p];
            cx[i] = (float)cp.x * invd;
            cy[i] = (float)cp.y * invd;
        }
    }

    float s[4] = {0.f, 0.f, 0.f, 0.f};
#pragma unroll 8
    for (int j = 0; j < 64; j++) {
        const float4 q = s4f[j];
#pragma unroll
        for (int i = 0; i < 4; i++) {
            float t = fmaf(cx[i], q.y, q.x);
            t = fmaf(cy[i], q.z, t);
            s[i] = fmaf(fmaxf(t, 0.f), q.w, s[i]);
        }
    }
#pragma unroll
    for (int i = 0; i < 4; i++) {
        const int p = p0 + i * 256;
        if (p < P) out[p] = s[i] + bias2;
    }
}

// ---------------- launch ---------------------------------------------------
extern "C" void kernel_launch(void* const* d_in, const int* in_sizes, int n_in,
                              void* d_out, int out_size)
{
    const float* node  = (const float*)d_in[0];
    const float* edge  = (const float*)d_in[1];
    const float* hist  = (const float*)d_in[2];
    const int*   cand  = (const int*)d_in[3];
    const int*   Np    = (const int*)d_in[4];
    const float* nodeW = (const float*)d_in[5];
    const float* nodeb = (const float*)d_in[6];
    const float* edgeW = (const float*)d_in[7];
    const float* edgeb = (const float*)d_in[8];
    const float* Wih   = (const float*)d_in[9];
    const float* Whh   = (const float*)d_in[10];
    const float* bih   = (const float*)d_in[11];
    const float* bhh   = (const float*)d_in[12];
    const float* fW1   = (const float*)d_in[13];
    const float* fb1   = (const float*)d_in[14];
    const float* fW2   = (const float*)d_in[15];
    const float* fb2   = (const float*)d_in[16];

    const int Nn = in_sizes[0] / 2;
    const int Ne = in_sizes[1] / 5;
    const int T  = in_sizes[2] / 3;
    const int P  = in_sizes[3] / 2;

    static bool attr_set = false;
    if (!attr_set) {
        cudaFuncSetAttribute(k1, cudaFuncAttributeMaxDynamicSharedMemorySize, K1_SMEM);
        attr_set = true;
    }

    const int GRID1 = 148;  // block 0 = LSTM, 147 = node/edge reduce
    k1<<<GRID1, NTH, K1_SMEM>>>(node, edge, hist, Nn, Ne, T,
                                nodeW, nodeb, edgeW, edgeb, Wih, Whh, bih, bhh);
    k2<<<1, 512>>>(GRID1 - 1, Nn, Ne, fW1, fb1, fW2);
    const int g3 = (P + 1023) / 1024;
    k3<<<g3, 256>>>(cand, P, Np, fb2, (float*)d_out);
}

// round 10
// speedup vs baseline: 1.3000x; 1.0128x over previous
#include <cuda_runtime.h>
#include <cstdint>

typedef unsigned long long u64;
typedef unsigned int u32;

// ---------------- device scratch (no allocations allowed) ----------------
__device__ float g_part_edge[160][64];
__device__ float g_part_node[160][64];
__device__ float g_zhist[64];
__device__ float g_base[64];
__device__ float g_av[64];
__device__ float g_bv[64];
__device__ float g_w2v[64];

// ---------------- helpers --------------------------------------------------
__device__ __forceinline__ float tanh_ap(float x) {
    float r; asm("tanh.approx.f32 %0,%1;" : "=f"(r) : "f"(x)); return r;
}
__device__ __forceinline__ float sigm(float x) { return 1.f / (1.f + __expf(-x)); }

__device__ __forceinline__ u32 bfpack(float lo, float hi) {
    u32 r; asm("cvt.rn.bf16x2.f32 %0, %1, %2;" : "=r"(r) : "f"(hi), "f"(lo)); return r;
}

__device__ __forceinline__ void mma8(float& d0, float& d1, float& d2, float& d3,
                                     u32 a0, u32 a1, u32 b,
                                     float c0, float c1, float c2, float c3) {
    asm("mma.sync.aligned.m16n8k8.row.col.f32.bf16.bf16.f32 "
        "{%0,%1,%2,%3},{%4,%5},{%6},{%7,%8,%9,%10};"
        : "=f"(d0), "=f"(d1), "=f"(d2), "=f"(d3)
        : "r"(a0), "r"(a1), "r"(b), "f"(c0), "f"(c1), "f"(c2), "f"(c3));
}

#define NTH   512             // threads per block -> 128-reg budget, NO spills
#define NW    16              // warps per block
#define CH    128             // rows per warp chunk
#define REDW  68

// ---- dynamic shared layout (bytes), union of two uses --------------------
//  phase:  scratch [0, 40960)      16 warps x 640 floats
//          red     [40960, 45312)  16*68 floats
//  LSTM :  hist    [0, 2432)       608 floats
//          shh     [2432, 2944)    2 x 64 floats
#define K1_SMEM 45312

extern __shared__ __align__(16) char dsm_raw[];

// ---------------- per-warp streaming tensor-core MLP reduction ------------
template<int INF>
__device__ __forceinline__ void phase(const float* __restrict__ X,
                                      const float* __restrict__ W,
                                      const float* __restrict__ bias,
                                      int nrows, float* __restrict__ partial,
                                      int nstreams, int ws)
{
    const int tid  = threadIdx.x;
    const int lane = tid & 31;
    const int w    = tid >> 5;
    const int gid  = lane >> 2;      // 0..7
    const int tig  = lane & 3;       // 0..3
    float* sw  = (float*)dsm_raw + w * 640;
    float* red = (float*)(dsm_raw + 40960);

    // B fragments (col = nt*8+gid, k = 2tig,2tig+1) + bias C (cols nt*8+2tig..+1)
    u32 bf[8];
    float c0[8], c1[8];
#pragma unroll
    for (int nt = 0; nt < 8; nt++) {
        const int ncol = nt * 8 + gid;
        const float vlo = (2 * tig < INF)     ? W[(2 * tig) * 64 + ncol]     : 0.f;
        const float vhi = (2 * tig + 1 < INF) ? W[(2 * tig + 1) * 64 + ncol] : 0.f;
        bf[nt] = bfpack(vlo, vhi);
        c0[nt] = bias[nt * 8 + 2 * tig];
        c1[nt] = bias[nt * 8 + 2 * tig + 1];
    }
    float acc[16];
#pragma unroll
    for (int i = 0; i < 16; i++) acc[i] = 0.f;

    const int nch = (nrows + CH - 1) / CH;
    const int nelem = nrows * INF;
    constexpr int NV = (CH * INF) / 128;    // float4 per lane per chunk
    float4 pf[NV];

    __syncthreads();   // protect scratch/red across phases

    int c = ws;
    if (c < nch) {
        const int b4 = c * (CH * INF / 4);
        if ((c + 1) * CH <= nrows) {
#pragma unroll
            for (int v = 0; v < NV; v++) pf[v] = ((const float4*)X)[b4 + lane + v * 32];
        } else {
#pragma unroll
            for (int v = 0; v < NV; v++) {
                const int e = (b4 + lane + v * 32) * 4;
                pf[v].x = (e     < nelem) ? X[e]     : 0.f;
                pf[v].y = (e + 1 < nelem) ? X[e + 1] : 0.f;
                pf[v].z = (e + 2 < nelem) ? X[e + 2] : 0.f;
                pf[v].w = (e + 3 < nelem) ? X[e + 3] : 0.f;
            }
        }
    }

    for (; c < nch; c += nstreams) {
#pragma unroll
        for (int v = 0; v < NV; v++) ((float4*)sw)[lane + v * 32] = pf[v];
        __syncwarp();

        const int cn = c + nstreams;
        if (cn < nch) {
            const int b4 = cn * (CH * INF / 4);
            if ((cn + 1) * CH <= nrows) {
#pragma unroll
                for (int v = 0; v < NV; v++) pf[v] = ((const float4*)X)[b4 + lane + v * 32];
            } else {
#pragma unroll
                for (int v = 0; v < NV; v++) {
                    const int e = (b4 + lane + v * 32) * 4;
                    pf[v].x = (e     < nelem) ? X[e]     : 0.f;
                    pf[v].y = (e + 1 < nelem) ? X[e + 1] : 0.f;
                    pf[v].z = (e + 2 < nelem) ? X[e + 2] : 0.f;
                    pf[v].w = (e + 3 < nelem) ? X[e + 3] : 0.f;
                }
            }
        }

        const int rows = min(CH, nrows - c * CH);
        if (rows == CH) {
#pragma unroll
            for (int t = 0; t < 8; t++) {
                const int r0 = t * 16 + gid;
                const float lo0 = (2 * tig < INF)     ? sw[r0 * INF + 2 * tig]           : 0.f;
                const float hi0 = (2 * tig + 1 < INF) ? sw[r0 * INF + 2 * tig + 1]       : 0.f;
                const float lo1 = (2 * tig < INF)     ? sw[(r0 + 8) * INF + 2 * tig]     : 0.f;
                const float hi1 = (2 * tig + 1 < INF) ? sw[(r0 + 8) * INF + 2 * tig + 1] : 0.f;
                const u32 a0 = bfpack(lo0, hi0);
                const u32 a1 = bfpack(lo1, hi1);
#pragma unroll
                for (int nt = 0; nt < 8; nt++) {
                    float d0, d1, d2, d3;
                    mma8(d0, d1, d2, d3, a0, a1, bf[nt], c0[nt], c1[nt], c0[nt], c1[nt]);
                    acc[2 * nt]     += fmaxf(d0, 0.f) + fmaxf(d2, 0.f);
                    acc[2 * nt + 1] += fmaxf(d1, 0.f) + fmaxf(d3, 0.f);
                }
            }
        } else {
#pragma unroll
            for (int t = 0; t < 8; t++) {
                const int r0 = t * 16 + gid;
                const float lo0 = (2 * tig < INF)     ? sw[r0 * INF + 2 * tig]           : 0.f;
                const float hi0 = (2 * tig + 1 < INF) ? sw[r0 * INF + 2 * tig + 1]       : 0.f;
                const float lo1 = (2 * tig < INF)     ? sw[(r0 + 8) * INF + 2 * tig]     : 0.f;
                const float hi1 = (2 * tig + 1 < INF) ? sw[(r0 + 8) * INF + 2 * tig + 1] : 0.f;
                const u32 a0 = bfpack(lo0, hi0);
                const u32 a1 = bfpack(lo1, hi1);
                const float m0 = (r0 < rows) ? 1.f : 0.f;
                const float m1 = (r0 + 8 < rows) ? 1.f : 0.f;
#pragma unroll
                for (int nt = 0; nt < 8; nt++) {
                    float d0, d1, d2, d3;
                    mma8(d0, d1, d2, d3, a0, a1, bf[nt], c0[nt], c1[nt], c0[nt], c1[nt]);
                    acc[2 * nt]     = fmaf(m0, fmaxf(d0, 0.f), acc[2 * nt]);
                    acc[2 * nt]     = fmaf(m1, fmaxf(d2, 0.f), acc[2 * nt]);
                    acc[2 * nt + 1] = fmaf(m0, fmaxf(d1, 0.f), acc[2 * nt + 1]);
                    acc[2 * nt + 1] = fmaf(m1, fmaxf(d3, 0.f), acc[2 * nt + 1]);
                }
            }
        }
        __syncwarp();
    }

    // reduce over gid (shfl xor 4,8,16), then cross-warp via shared
    __syncthreads();
#pragma unroll
    for (int nt = 0; nt < 8; nt++) {
        float lo = acc[2 * nt], hi = acc[2 * nt + 1];
#pragma unroll
        for (int off = 4; off <= 16; off <<= 1) {
            lo += __shfl_xor_sync(0xffffffffu, lo, off);
            hi += __shfl_xor_sync(0xffffffffu, hi, off);
        }
        if (gid == 0) {
            red[w * REDW + nt * 8 + 2 * tig]     = lo;
            red[w * REDW + nt * 8 + 2 * tig + 1] = hi;
        }
    }
    __syncthreads();
    if (tid < 64) {
        float sum = 0.f;
#pragma unroll 8
        for (int r2 = 0; r2 < NW; r2++) sum += red[r2 * REDW + tid];
        partial[tid] = sum;
    }
}

// ---------------- kernel 1: LSTM (block 0) + node/edge reduce -------------
__global__ void __launch_bounds__(NTH, 1) k1(
    const float* __restrict__ node, const float* __restrict__ edge,
    const float* __restrict__ hist, int Nn, int Ne, int T,
    const float* __restrict__ nodeW, const float* __restrict__ nodeb,
    const float* __restrict__ edgeW, const float* __restrict__ edgeb,
    const float* __restrict__ Wih, const float* __restrict__ Whh,
    const float* __restrict__ bih, const float* __restrict__ bhh)
{
    const int tid = threadIdx.x;

    if (blockIdx.x == 0) {
        // ------- LSTM: 512 threads = (j, gate, half) -----------------------
        float* sh_hist = (float*)dsm_raw;             // 608 floats
        float* sh_h    = (float*)(dsm_raw + 2432);    // 2 x 64 floats

        for (int i = tid; i < T * 3 && i < 608; i += NTH) sh_hist[i] = hist[i];
        if (tid < 128) sh_h[tid] = 0.f;
        __syncthreads();

        const int j    = tid >> 3;
        const int gate = (tid >> 1) & 3;
        const int half = tid & 1;
        const int row  = gate * 64 + j;
        const int lane = tid & 31;
        const int base = lane & 24;

        float wv[32];
        {
            const float* wr = Whh + row * 64 + half * 32;
#pragma unroll
            for (int k = 0; k < 32; k++) wv[k] = wr[k];
        }
        const float wi0 = Wih[row * 3], wi1 = Wih[row * 3 + 1], wi2 = Wih[row * 3 + 2];
        const float bsum = bih[row] + bhh[row];
        const bool hsh = (T * 3 <= 608);
        const bool is_g = (gate == 2);
        const bool is_owner = ((tid & 7) == 0);
        float c = 0.f;

        for (int t = 0; t < T; t++) {
            const float* xp = hsh ? (sh_hist + t * 3) : (hist + t * 3);
            const float pre = fmaf(wi0, xp[0], fmaf(wi1, xp[1], fmaf(wi2, xp[2], bsum)));
            const float2* hh = (const float2*)(sh_h + (t & 1) * 64 + half * 32);
            float a0 = 0.f, a1 = 0.f, a2 = 0.f, a3 = 0.f;
#pragma unroll
            for (int k = 0; k < 16; k += 4) {
                float2 h0 = hh[k], h1 = hh[k + 1], h2 = hh[k + 2], h3 = hh[k + 3];
                a0 = fmaf(wv[2 * k],     h0.x, a0); a0 = fmaf(wv[2 * k + 1], h0.y, a0);
                a1 = fmaf(wv[2 * k + 2], h1.x, a1); a1 = fmaf(wv[2 * k + 3], h1.y, a1);
                a2 = fmaf(wv[2 * k + 4], h2.x, a2); a2 = fmaf(wv[2 * k + 5], h2.y, a2);
                a3 = fmaf(wv[2 * k + 6], h3.x, a3); a3 = fmaf(wv[2 * k + 7], h3.y, a3);
            }
            float s = (a0 + a1) + (a2 + a3);
            s += __shfl_xor_sync(0xffffffffu, s, 1);
            const float z = pre + s;
            const float a = is_g ? tanh_ap(z) : sigm(z);
            const float gi = __shfl_sync(0xffffffffu, a, base + 0);
            const float gf = __shfl_sync(0xffffffffu, a, base + 2);
            const float gg = __shfl_sync(0xffffffffu, a, base + 4);
            const float go = __shfl_sync(0xffffffffu, a, base + 6);
            if (is_owner) {
                c = fmaf(gf, c, gi * gg);
                sh_h[((t + 1) & 1) * 64 + j] = go * tanh_ap(c);
            }
            __syncthreads();
        }
        if (is_owner) g_zhist[j] = sh_h[(T & 1) * 64 + j];
    } else {
        const int nstreams = (gridDim.x - 1) * NW;
        const int ws = (blockIdx.x - 1) * NW + (tid >> 5);
        phase<2>(node, nodeW, nodeb, Nn, g_part_node[blockIdx.x - 1], nstreams, ws);
        phase<5>(edge, edgeW, edgeb, Ne, g_part_edge[blockIdx.x - 1], nstreams, ws);
    }
}

// ---------------- kernel 2: finalize ctx + precompute base/a/b/w2 ---------
__global__ void __launch_bounds__(512) k2(int nb, int Nn, int Ne,
                   const float* __restrict__ W1, const float* __restrict__ b1,
                   const float* __restrict__ W2f)
{
    __shared__ float ctx[192];
    __shared__ float t1[512], t2[512];
    const int tid = threadIdx.x;
    const int c = tid >> 6, j = tid & 63;   // 8 groups

    float se = 0.f, sn = 0.f;
#pragma unroll 4
    for (int b = c; b < nb; b += 8) {
        se += g_part_edge[b][j];
        sn += g_part_node[b][j];
    }
    t1[tid] = se; t2[tid] = sn;
    __syncthreads();
    if (tid < 64) {
        float e = 0.f, n = 0.f;
#pragma unroll
        for (int g = 0; g < 8; g++) { e += t1[g * 64 + tid]; n += t2[g * 64 + tid]; }
        ctx[tid]       = n * (1.f / (float)Nn);
        ctx[64 + tid]  = e * (1.f / (float)Ne);
        ctx[128 + tid] = g_zhist[tid];
    }
    __syncthreads();
    float p = 0.f;
    const int i0 = c * 24;
#pragma unroll 8
    for (int i = i0; i < i0 + 24; i++) p = fmaf(ctx[i], W1[i * 64 + j], p);
    __syncthreads();
    t1[tid] = p;
    __syncthreads();
    if (tid < 64) {
        float s = b1[tid];
#pragma unroll
        for (int g = 0; g < 8; g++) s += t1[g * 64 + tid];
        g_base[tid] = s;
        g_av[tid]   = W1[192 * 64 + tid];
        g_bv[tid]   = W1[193 * 64 + tid];
        g_w2v[tid]  = W2f[tid];
    }
}

// ---------------- kernel 3: candidate scoring (scalar, float4 weights) ----
__global__ void __launch_bounds__(256) k3(const int* __restrict__ cand, int P,
                                          const int* __restrict__ Np,
                                          const float* __restrict__ fb2,
                                          float* __restrict__ out)
{
    __shared__ __align__(16) float4 s4f[64];   // {base, av, bv, w2v}[j]
    const int tid = threadIdx.x;
    if (tid < 64)
        s4f[tid] = make_float4(g_base[tid], g_av[tid], g_bv[tid], g_w2v[tid]);
    const float invd = 1.f / ((float)(*Np) - 1.f + 1e-9f);
    const float bias2 = fb2[0];
    __syncthreads();

    const int p0 = blockIdx.x * 1024 + tid;
    float cx[4], cy[4];
#pragma unroll
    for (int i = 0; i < 4; i++) {
        const int p = p0 + i * 256;
        cx[i] = 0.f; cy[i] = 0.f;
        if (p < P) {
            const int2 cp = ((const int2*)cand)[p];
            cx[i] = (float)cp.x * invd;
            cy[i] = (float)cp.y * invd;
        }
    }

    float s[4] = {0.f, 0.f, 0.f, 0.f};
#pragma unroll 8
    for (int j = 0; j < 64; j++) {
        const float4 q = s4f[j];
#pragma unroll
        for (int i = 0; i < 4; i++) {
            float t = fmaf(cx[i], q.y, q.x);
            t = fmaf(cy[i], q.z, t);
            s[i] = fmaf(fmaxf(t, 0.f), q.w, s[i]);
        }
    }
#pragma unroll
    for (int i = 0; i < 4; i++) {
        const int p = p0 + i * 256;
        if (p < P) out[p] = s[i] + bias2;
    }
}

// ---------------- launch ---------------------------------------------------
extern "C" void kernel_launch(void* const* d_in, const int* in_sizes, int n_in,
                              void* d_out, int out_size)
{
    const float* node  = (const float*)d_in[0];
    const float* edge  = (const float*)d_in[1];
    const float* hist  = (const float*)d_in[2];
    const int*   cand  = (const int*)d_in[3];
    const int*   Np    = (const int*)d_in[4];
    const float* nodeW = (const float*)d_in[5];
    const float* nodeb = (const float*)d_in[6];
    const float* edgeW = (const float*)d_in[7];
    const float* edgeb = (const float*)d_in[8];
    const float* Wih   = (const float*)d_in[9];
    const float* Whh   = (const float*)d_in[10];
    const float* bih   = (const float*)d_in[11];
    const float* bhh   = (const float*)d_in[12];
    const float* fW1   = (const float*)d_in[13];
    const float* fb1   = (const float*)d_in[14];
    const float* fW2   = (const float*)d_in[15];
    const float* fb2   = (const float*)d_in[16];

    const int Nn = in_sizes[0] / 2;
    const int Ne = in_sizes[1] / 5;
    const int T  = in_sizes[2] / 3;
    const int P  = in_sizes[3] / 2;

    static bool attr_set = false;
    if (!attr_set) {
        cudaFuncSetAttribute(k1, cudaFuncAttributeMaxDynamicSharedMemorySize, K1_SMEM);
        attr_set = true;
    }

    const int GRID1 = 148;  // block 0 = LSTM, 147 = node/edge reduce
    k1<<<GRID1, NTH, K1_SMEM>>>(node, edge, hist, Nn, Ne, T,
                                nodeW, nodeb, edgeW, edgeb, Wih, Whh, bih, bhh);
    k2<<<1, 512>>>(GRID1 - 1, Nn, Ne, fW1, fb1, fW2);
    const int g3 = (P + 1023) / 1024;
    k3<<<g3, 256>>>(cand, P, Np, fb2, (float*)d_out);
}

// round 11
// speedup vs baseline: 1.6594x; 1.2765x over previous
#include <cuda_runtime.h>
#include <cstdint>

typedef unsigned long long u64;

// ---------------- device scratch (no allocations allowed) ----------------
__device__ float g_part_edge[160][64];
__device__ float g_part_node[160][64];
__device__ float g_zhist[64];
__device__ float g_base[64];
__device__ float g_av[64];
__device__ float g_bv[64];
__device__ float g_w2v[64];

// ---------------- f32x2 packed helpers ------------------------------------
__device__ __forceinline__ u64 pk2(float a, float b) {
    u64 r; asm("mov.b64 %0,{%1,%2};" : "=l"(r) : "f"(a), "f"(b)); return r;
}
__device__ __forceinline__ void up2(u64 v, float& a, float& b) {
    asm("mov.b64 {%0,%1},%2;" : "=f"(a), "=f"(b) : "l"(v));
}
__device__ __forceinline__ u64 f2fma(u64 a, u64 b, u64 c) {
    u64 d; asm("fma.rn.f32x2 %0,%1,%2,%3;" : "=l"(d) : "l"(a), "l"(b), "l"(c)); return d;
}
__device__ __forceinline__ float tanh_ap(float x) {
    float r; asm("tanh.approx.f32 %0,%1;" : "=f"(r) : "f"(x)); return r;
}
__device__ __forceinline__ float sigm(float x) { return 1.f / (1.f + __expf(-x)); }

// ---------------- staged MLP mean-pool reduction (110.6us config) ---------
// Thread layout: group of 8 threads (tid&7 selects 8-output j-subset) shares
// 2 rows per iteration; f32x2 lanes = (rowA, rowB). W broadcast-packed in regs.
template<int INF, int RPS>
__device__ __forceinline__ void phase(const float* __restrict__ X,
                                      const float* __restrict__ W,
                                      const float* __restrict__ bias,
                                      int nrows, float* __restrict__ partial,
                                      int nb, int b, float* sh)
{
    const int tid = threadIdx.x;
    const int j0 = (tid & 7) * 8;

    u64 w2[INF * 8];
    u64 b2[8];
#pragma unroll
    for (int k = 0; k < INF; k++)
#pragma unroll
        for (int jj = 0; jj < 8; jj++) {
            float w = W[k * 64 + j0 + jj];
            w2[k * 8 + jj] = pk2(w, w);
        }
#pragma unroll
    for (int jj = 0; jj < 8; jj++) {
        float bb = bias[j0 + jj];
        b2[jj] = pk2(bb, bb);
    }

    u64 acc[8];
#pragma unroll
    for (int jj = 0; jj < 8; jj++) acc[jj] = 0ull;

    const int nstages = (nrows + RPS - 1) / RPS;
    for (int s = b; s < nstages; s += nb) {
        const int r0 = s * RPS;
        const int rows = min(RPS, nrows - r0);
        __syncthreads();
        if (rows == RPS) {
            const float4* src = (const float4*)(X + (size_t)r0 * INF);
            float4* dst = (float4*)sh;
#pragma unroll
            for (int i = tid; i < RPS * INF / 4; i += 256) dst[i] = src[i];
        } else {
            const int nf = rows * INF;
            for (int i = tid; i < RPS * INF; i += 256)
                sh[i] = (i < nf) ? X[(size_t)r0 * INF + i] : 0.f;
        }
        __syncthreads();

#pragma unroll 2
        for (int it = 0; it < RPS / 64; ++it) {
            const int rp = it * 32 + (tid >> 3);
            const int ra = rp * 2, rb = ra + 1;
            const float m0 = (ra < rows) ? 1.f : 0.f;
            const float m1 = (rb < rows) ? 1.f : 0.f;
            const u64 mask = pk2(m0, m1);
            u64 x2[INF];
#pragma unroll
            for (int k = 0; k < INF; k++)
                x2[k] = pk2(sh[ra * INF + k], sh[rb * INF + k]);
#pragma unroll
            for (int jj = 0; jj < 8; jj++) {
                u64 y = b2[jj];
#pragma unroll
                for (int k = 0; k < INF; k++)
                    y = f2fma(x2[k], w2[k * 8 + jj], y);
                float yl, yh; up2(y, yl, yh);
                u64 h = pk2(fmaxf(yl, 0.f), fmaxf(yh, 0.f));
                acc[jj] = f2fma(h, mask, acc[jj]);   // masked accumulate
            }
        }
    }

    // deterministic cross-thread reduce (fixed order; no atomics)
    __syncthreads();
#pragma unroll
    for (int jj = 0; jj < 8; jj++) {
        float a, bb; up2(acc[jj], a, bb);
        sh[tid * 8 + jj] = a + bb;
    }
    __syncthreads();
    if (tid < 64) {
        const int gi = tid >> 3, jj = tid & 7;
        float s = 0.f;
#pragma unroll 4
        for (int g = 0; g < 32; g++) s += sh[(g * 8 + gi) * 8 + jj];
        partial[tid] = s;
    }
    __syncthreads();
}

// ---------------- kernel 1: LSTM (block 0) + node/edge reduce ------------
__global__ void __launch_bounds__(256, 1) k1(
    const float* __restrict__ node, const float* __restrict__ edge,
    const float* __restrict__ hist, int Nn, int Ne, int T,
    const float* __restrict__ nodeW, const float* __restrict__ nodeb,
    const float* __restrict__ edgeW, const float* __restrict__ edgeb,
    const float* __restrict__ Wih, const float* __restrict__ Whh,
    const float* __restrict__ bih, const float* __restrict__ bhh)
{
    __shared__ float sh[5120];
    __shared__ float sh_hist[640];
    __shared__ float sh_g[256];
    __shared__ __align__(8) float sh_h[64];

    const int tid = threadIdx.x;

    if (blockIdx.x == 0) {
        // ---------------- LSTM, 256 threads = one gate row each ----------
        u64 w2[32];
        const float2* wr = (const float2*)(Whh + tid * 64);
#pragma unroll
        for (int k = 0; k < 32; k++) { float2 p = wr[k]; w2[k] = pk2(p.x, p.y); }
        const float wi0 = Wih[tid * 3], wi1 = Wih[tid * 3 + 1], wi2 = Wih[tid * 3 + 2];
        const float bsum = bih[tid] + bhh[tid];

        const bool hsh = (T * 3 <= 640);
        for (int i = tid; i < T * 3 && i < 640; i += 256) sh_hist[i] = hist[i];
        if (tid < 64) sh_h[tid] = 0.f;
        float c = 0.f;
        __syncthreads();

        const bool is_tanh_gate = (tid >= 128 && tid < 192);
        for (int t = 0; t < T; t++) {
            const float* xp = hsh ? (sh_hist + t * 3) : (hist + t * 3);
            float pre = fmaf(wi0, xp[0], fmaf(wi1, xp[1], fmaf(wi2, xp[2], bsum)));
            const u64* hp = (const u64*)sh_h;
            u64 a0 = 0, a1 = 0, a2 = 0, a3 = 0;
#pragma unroll
            for (int k = 0; k < 32; k += 4) {
                a0 = f2fma(w2[k],     hp[k],     a0);
                a1 = f2fma(w2[k + 1], hp[k + 1], a1);
                a2 = f2fma(w2[k + 2], hp[k + 2], a2);
                a3 = f2fma(w2[k + 3], hp[k + 3], a3);
            }
            float s0, s1, s2, s3, s4, s5, s6, s7;
            up2(a0, s0, s1); up2(a1, s2, s3); up2(a2, s4, s5); up2(a3, s6, s7);
            const float z = pre + ((s0 + s1) + (s2 + s3)) + ((s4 + s5) + (s6 + s7));
            sh_g[tid] = is_tanh_gate ? tanh_ap(z) : sigm(z);
            __syncthreads();
            if (tid < 64) {
                const float ig = sh_g[tid], fg = sh_g[64 + tid];
                const float gg = sh_g[128 + tid], og = sh_g[192 + tid];
                c = fmaf(fg, c, ig * gg);
                sh_h[tid] = og * tanh_ap(c);
            }
            __syncthreads();
        }
        if (tid < 64) g_zhist[tid] = sh_h[tid];
    } else {
        const int b = blockIdx.x - 1;
        const int nb = gridDim.x - 1;
        phase<2, 2048>(node, nodeW, nodeb, Nn, g_part_node[b], nb, b, sh);
        phase<5, 1024>(edge, edgeW, edgeb, Ne, g_part_edge[b], nb, b, sh);
    }
}

// ---------------- kernel 2: finalize ctx + precompute base/a/b/w2 --------
// nb = 147 is a compile-time constant (grid is fixed at 148). 512 threads,
// fully unrolled independent loads -> MLP-rich, no latency chains.
#define NB 147

__global__ void __launch_bounds__(512) k2(int Nn, int Ne,
                   const float* __restrict__ W1, const float* __restrict__ b1,
                   const float* __restrict__ W2f)
{
    __shared__ float ctx[192];
    __shared__ float t1[512], t2[512];
    const int tid = threadIdx.x;
    const int c = tid >> 6, j = tid & 63;   // 8 groups of 64

    float se = 0.f, sn = 0.f;
#pragma unroll
    for (int i = 0; i < 19; i++) {          // ceil(147/8)=19, guarded
        const int b = c + i * 8;
        if (b < NB) {
            se += g_part_edge[b][j];
            sn += g_part_node[b][j];
        }
    }
    t1[tid] = se; t2[tid] = sn;
    __syncthreads();
    if (tid < 64) {
        float e = 0.f, n = 0.f;
#pragma unroll
        for (int g = 0; g < 8; g++) { e += t1[g * 64 + tid]; n += t2[g * 64 + tid]; }
        ctx[tid]       = n * (1.f / (float)Nn);
        ctx[64 + tid]  = e * (1.f / (float)Ne);
        ctx[128 + tid] = g_zhist[tid];
    }
    __syncthreads();
    // base[j] = b1[j] + sum_i ctx[i]*W1[i][j], i split 8 ways (24 each)
    float p = 0.f;
    const int i0 = c * 24;
#pragma unroll
    for (int i = 0; i < 24; i++) p = fmaf(ctx[i0 + i], W1[(i0 + i) * 64 + j], p);
    __syncthreads();
    t1[tid] = p;
    __syncthreads();
    if (tid < 64) {
        float s = b1[tid];
#pragma unroll
        for (int g = 0; g < 8; g++) s += t1[g * 64 + tid];
        g_base[tid] = s;
        g_av[tid]   = W1[192 * 64 + tid];
        g_bv[tid]   = W1[193 * 64 + tid];
        g_w2v[tid]  = W2f[tid];
    }
}

// ---------------- kernel 3: candidate scoring (ILP=4, u64 shared wt) ------
__global__ void __launch_bounds__(256) k3(const int* __restrict__ cand, int P,
                                          const int* __restrict__ Np,
                                          const float* __restrict__ fb2,
                                          float* __restrict__ out)
{
    __shared__ __align__(16) u64 s4[128];   // [jp]{base2, a2, b2, w22}
    const int tid = threadIdx.x;
    if (tid < 32) {
        s4[tid * 4 + 0] = pk2(g_base[2 * tid], g_base[2 * tid + 1]);
        s4[tid * 4 + 1] = pk2(g_av[2 * tid],   g_av[2 * tid + 1]);
        s4[tid * 4 + 2] = pk2(g_bv[2 * tid],   g_bv[2 * tid + 1]);
        s4[tid * 4 + 3] = pk2(g_w2v[2 * tid],  g_w2v[2 * tid + 1]);
    }
    const float invd = 1.f / ((float)(*Np) - 1.f + 1e-9f);
    const float bias2 = fb2[0];
    __syncthreads();

    int p = blockIdx.x * 1024 + tid;
#pragma unroll
    for (int i = 0; i < 4; i++, p += 256) {
        if (p < P) {
            const int2 cp = ((const int2*)cand)[p];
            const float cx = (float)cp.x * invd;
            const float cy = (float)cp.y * invd;
            const u64 cx2 = pk2(cx, cx), cy2 = pk2(cy, cy);
            u64 acc0 = 0, acc1 = 0;
#pragma unroll
            for (int jp = 0; jp < 32; jp += 2) {
                {
                    u64 tt = f2fma(cx2, s4[jp * 4 + 1], s4[jp * 4 + 0]);
                    tt = f2fma(cy2, s4[jp * 4 + 2], tt);
                    float l, h; up2(tt, l, h);
                    u64 hh = pk2(fmaxf(l, 0.f), fmaxf(h, 0.f));
                    acc0 = f2fma(hh, s4[jp * 4 + 3], acc0);
                }
                {
                    u64 tt = f2fma(cx2, s4[(jp + 1) * 4 + 1], s4[(jp + 1) * 4 + 0]);
                    tt = f2fma(cy2, s4[(jp + 1) * 4 + 2], tt);
                    float l, h; up2(tt, l, h);
                    u64 hh = pk2(fmaxf(l, 0.f), fmaxf(h, 0.f));
                    acc1 = f2fma(hh, s4[(jp + 1) * 4 + 3], acc1);
                }
            }
            float r0, r1, r2, r3;
            up2(acc0, r0, r1); up2(acc1, r2, r3);
            out[p] = (r0 + r1) + (r2 + r3) + bias2;
        }
    }
}

// ---------------- launch --------------------------------------------------
extern "C" void kernel_launch(void* const* d_in, const int* in_sizes, int n_in,
                              void* d_out, int out_size)
{
    const float* node  = (const float*)d_in[0];
    const float* edge  = (const float*)d_in[1];
    const float* hist  = (const float*)d_in[2];
    const int*   cand  = (const int*)d_in[3];
    const int*   Np    = (const int*)d_in[4];
    const float* nodeW = (const float*)d_in[5];
    const float* nodeb = (const float*)d_in[6];
    const float* edgeW = (const float*)d_in[7];
    const float* edgeb = (const float*)d_in[8];
    const float* Wih   = (const float*)d_in[9];
    const float* Whh   = (const float*)d_in[10];
    const float* bih   = (const float*)d_in[11];
    const float* bhh   = (const float*)d_in[12];
    const float* fW1   = (const float*)d_in[13];
    const float* fb1   = (const float*)d_in[14];
    const float* fW2   = (const float*)d_in[15];
    const float* fb2   = (const float*)d_in[16];

    const int Nn = in_sizes[0] / 2;
    const int Ne = in_sizes[1] / 5;
    const int T  = in_sizes[2] / 3;
    const int P  = in_sizes[3] / 2;

    const int GRID1 = 148;  // block 0 = LSTM, 147 = node/edge reduce (== NB)
    k1<<<GRID1, 256>>>(node, edge, hist, Nn, Ne, T,
                       nodeW, nodeb, edgeW, edgeb, Wih, Whh, bih, bhh);
    k2<<<1, 512>>>(Nn, Ne, fW1, fb1, fW2);
    const int g3 = (P + 1023) / 1024;
    k3<<<g3, 256>>>(cand, P, Np, fb2, (float*)d_out);
}

// round 12
// speedup vs baseline: 1.7151x; 1.0336x over previous
#include <cuda_runtime.h>
#include <cstdint>

typedef unsigned long long u64;

// ---------------- device scratch (no allocations allowed) ----------------
__device__ float g_part_edge[160][64];
__device__ float g_part_node[160][64];
__device__ float g_zhist[64];
__device__ float g_base[64];
__device__ float g_av[64];
__device__ float g_bv[64];
__device__ float g_w2v[64];

// ---------------- f32x2 packed helpers ------------------------------------
__device__ __forceinline__ u64 pk2(float a, float b) {
    u64 r; asm("mov.b64 %0,{%1,%2};" : "=l"(r) : "f"(a), "f"(b)); return r;
}
__device__ __forceinline__ void up2(u64 v, float& a, float& b) {
    asm("mov.b64 {%0,%1},%2;" : "=f"(a), "=f"(b) : "l"(v));
}
__device__ __forceinline__ u64 f2fma(u64 a, u64 b, u64 c) {
    u64 d; asm("fma.rn.f32x2 %0,%1,%2,%3;" : "=l"(d) : "l"(a), "l"(b), "l"(c)); return d;
}
__device__ __forceinline__ u64 add2(u64 a, u64 b) {
    u64 d; asm("add.rn.f32x2 %0,%1,%2;" : "=l"(d) : "l"(a), "l"(b)); return d;
}
// packed relu via paired-register max
__device__ __forceinline__ u64 relu2(u64 v) {
    u64 r;
    asm("{\n\t.reg .f32 l,h;\n\t"
        "mov.b64 {l,h}, %1;\n\t"
        "max.f32 l, l, 0f00000000;\n\t"
        "max.f32 h, h, 0f00000000;\n\t"
        "mov.b64 %0, {l,h};\n\t}"
        : "=l"(r) : "l"(v));
    return r;
}
__device__ __forceinline__ float tanh_ap(float x) {
    float r; asm("tanh.approx.f32 %0,%1;" : "=f"(r) : "f"(x)); return r;
}
__device__ __forceinline__ float sigm(float x) { return 1.f / (1.f + __expf(-x)); }

// ---------------- staged MLP mean-pool reduction (93.6us config) ----------
// 512 threads. group of 16 threads (tid&15) -> 4 outputs each (64 total).
// lanes of f32x2 = (rowA, rowB). Shared is TRANSPOSED: sht[k][row] so the
// lane pair is one natural LDS.64 (no packing movs).
#define RPS   1024
#define KPAD  1032

template<int INF>
__device__ __forceinline__ void phase(const float* __restrict__ X,
                                      const float* __restrict__ W,
                                      const float* __restrict__ bias,
                                      int nrows, float* __restrict__ partial,
                                      int nb, int b,
                                      float* __restrict__ sht,  // INF*KPAD floats
                                      float* __restrict__ red)  // 2048 floats
{
    const int tid = threadIdx.x;
    const int j0 = (tid & 15) * 4;
    const int rpb = tid >> 4;          // 0..31

    u64 w2[INF * 4];
    u64 b2[4];
#pragma unroll
    for (int k = 0; k < INF; k++)
#pragma unroll
        for (int jj = 0; jj < 4; jj++) {
            float w = W[k * 64 + j0 + jj];
            w2[k * 4 + jj] = pk2(w, w);
        }
#pragma unroll
    for (int jj = 0; jj < 4; jj++) {
        float bb = bias[j0 + jj];
        b2[jj] = pk2(bb, bb);
    }

    u64 acc[4] = {0ull, 0ull, 0ull, 0ull};

    const int nstages = (nrows + RPS - 1) >> 10;
    float rg[2][INF];

    // prefetch first stage
    if (b < nstages) {
        const int r0 = b << 10;
#pragma unroll
        for (int t2 = 0; t2 < 2; t2++) {
            const int gr = r0 + tid + t2 * 512;
            if (gr < nrows) {
#pragma unroll
                for (int k = 0; k < INF; k++) rg[t2][k] = X[gr * INF + k];
            } else {
#pragma unroll
                for (int k = 0; k < INF; k++) rg[t2][k] = 0.f;
            }
        }
    }

    for (int s = b; s < nstages; s += nb) {
        __syncthreads();
#pragma unroll
        for (int t2 = 0; t2 < 2; t2++) {
            const int j = tid + t2 * 512;
#pragma unroll
            for (int k = 0; k < INF; k++) sht[k * KPAD + j] = rg[t2][k];
        }
        __syncthreads();

        // prefetch next stage (overlaps compute)
        const int sn = s + nb;
        if (sn < nstages) {
            const int r0 = sn << 10;
#pragma unroll
            for (int t2 = 0; t2 < 2; t2++) {
                const int gr = r0 + tid + t2 * 512;
                if (gr < nrows) {
#pragma unroll
                    for (int k = 0; k < INF; k++) rg[t2][k] = X[gr * INF + k];
                } else {
#pragma unroll
                    for (int k = 0; k < INF; k++) rg[t2][k] = 0.f;
                }
            }
        }

        const int rows = min(RPS, nrows - (s << 10));
        if (rows == RPS) {
#pragma unroll 4
            for (int it = 0; it < RPS / 64; ++it) {
                const int rp = it * 32 + rpb;
                u64 x2[INF];
#pragma unroll
                for (int k = 0; k < INF; k++)
                    x2[k] = ((const u64*)(sht + k * KPAD))[rp];
#pragma unroll
                for (int jj = 0; jj < 4; jj++) {
                    u64 y = b2[jj];
#pragma unroll
                    for (int k = 0; k < INF; k++)
                        y = f2fma(x2[k], w2[k * 4 + jj], y);
                    acc[jj] = add2(relu2(y), acc[jj]);
                }
            }
        } else {
#pragma unroll 4
            for (int it = 0; it < RPS / 64; ++it) {
                const int rp = it * 32 + rpb;
                const float m0 = (2 * rp < rows) ? 1.f : 0.f;
                const float m1 = (2 * rp + 1 < rows) ? 1.f : 0.f;
                const u64 mask = pk2(m0, m1);
                u64 x2[INF];
#pragma unroll
                for (int k = 0; k < INF; k++)
                    x2[k] = ((const u64*)(sht + k * KPAD))[rp];
#pragma unroll
                for (int jj = 0; jj < 4; jj++) {
                    u64 y = b2[jj];
#pragma unroll
                    for (int k = 0; k < INF; k++)
                        y = f2fma(x2[k], w2[k * 4 + jj], y);
                    acc[jj] = f2fma(relu2(y), mask, acc[jj]);
                }
            }
        }
    }

    // deterministic cross-thread reduce
    __syncthreads();
    {
        float4 v;
        float a, bb;
        up2(acc[0], a, bb); v.x = a + bb;
        up2(acc[1], a, bb); v.y = a + bb;
        up2(acc[2], a, bb); v.z = a + bb;
        up2(acc[3], a, bb); v.w = a + bb;
        ((float4*)red)[tid] = v;
    }
    __syncthreads();
    if (tid < 64) {
        float s = 0.f;
#pragma unroll 8
        for (int rp = 0; rp < 32; rp++) s += red[rp * 64 + tid];
        partial[tid] = s;
    }
    __syncthreads();
}

// ---------------- kernel 1: LSTM (block 0) + node/edge reduce -------------
__global__ void __launch_bounds__(512, 1) k1(
    const float* __restrict__ node, const float* __restrict__ edge,
    const float* __restrict__ hist, int Nn, int Ne, int T,
    const float* __restrict__ nodeW, const float* __restrict__ nodeb,
    const float* __restrict__ edgeW, const float* __restrict__ edgeb,
    const float* __restrict__ Wih, const float* __restrict__ Whh,
    const float* __restrict__ bih, const float* __restrict__ bhh)
{
    __shared__ __align__(16) float sht[5 * KPAD];
    __shared__ __align__(16) float red[2048];
    __shared__ float sh_hist[608];
    __shared__ float sh_g[256];
    __shared__ __align__(8) float sh_h[64];

    const int tid = threadIdx.x;

    if (blockIdx.x == 0) {
        // ---------------- LSTM: 256 gate threads (of 512) -----------------
        u64 w2[32];
        float wi0 = 0.f, wi1 = 0.f, wi2 = 0.f, bsum = 0.f;
        if (tid < 256) {
            const float2* wr = (const float2*)(Whh + tid * 64);
#pragma unroll
            for (int k = 0; k < 32; k++) { float2 p = wr[k]; w2[k] = pk2(p.x, p.y); }
            wi0 = Wih[tid * 3]; wi1 = Wih[tid * 3 + 1]; wi2 = Wih[tid * 3 + 2];
            bsum = bih[tid] + bhh[tid];
        }
        const bool hsh = (T * 3 <= 608);
        for (int i = tid; i < T * 3 && i < 608; i += 512) sh_hist[i] = hist[i];
        if (tid < 64) sh_h[tid] = 0.f;
        float c = 0.f;
        __syncthreads();

        const bool is_tanh_gate = (tid >= 128 && tid < 192);
        for (int t = 0; t < T; t++) {
            if (tid < 256) {
                const float* xp = hsh ? (sh_hist + t * 3) : (hist + t * 3);
                float pre = fmaf(wi0, xp[0], fmaf(wi1, xp[1], fmaf(wi2, xp[2], bsum)));
                const u64* hp = (const u64*)sh_h;
                u64 a0 = 0, a1 = 0, a2 = 0, a3 = 0;
#pragma unroll
                for (int k = 0; k < 32; k += 4) {
                    a0 = f2fma(w2[k],     hp[k],     a0);
                    a1 = f2fma(w2[k + 1], hp[k + 1], a1);
                    a2 = f2fma(w2[k + 2], hp[k + 2], a2);
                    a3 = f2fma(w2[k + 3], hp[k + 3], a3);
                }
                float s0, s1, s2, s3, s4, s5, s6, s7;
                up2(a0, s0, s1); up2(a1, s2, s3); up2(a2, s4, s5); up2(a3, s6, s7);
                const float z = pre + ((s0 + s1) + (s2 + s3)) + ((s4 + s5) + (s6 + s7));
                sh_g[tid] = is_tanh_gate ? tanh_ap(z) : sigm(z);
            }
            __syncthreads();
            if (tid < 64) {
                const float ig = sh_g[tid], fg = sh_g[64 + tid];
                const float gg = sh_g[128 + tid], og = sh_g[192 + tid];
                c = fmaf(fg, c, ig * gg);
                sh_h[tid] = og * tanh_ap(c);
            }
            __syncthreads();
        }
        if (tid < 64) g_zhist[tid] = sh_h[tid];
    } else {
        const int b = blockIdx.x - 1;
        const int nb = gridDim.x - 1;
        phase<2>(node, nodeW, nodeb, Nn, g_part_node[b], nb, b, sht, red);
        phase<5>(edge, edgeW, edgeb, Ne, g_part_edge[b], nb, b, sht, red);
    }
}

// ---------------- kernel 2: finalize ctx + precompute base/a/b/w2 ---------
// nb = 147 compile-time; 512 threads; unrolled independent loads.
#define NB 147

__global__ void __launch_bounds__(512) k2(int Nn, int Ne,
                   const float* __restrict__ W1, const float* __restrict__ b1,
                   const float* __restrict__ W2f)
{
    __shared__ float ctx[192];
    __shared__ float t1[512], t2[512];
    const int tid = threadIdx.x;
    const int c = tid >> 6, j = tid & 63;   // 8 groups of 64

    float se = 0.f, sn = 0.f;
#pragma unroll
    for (int i = 0; i < 19; i++) {          // ceil(147/8)=19, guarded
        const int b = c + i * 8;
        if (b < NB) {
            se += g_part_edge[b][j];
            sn += g_part_node[b][j];
        }
    }
    t1[tid] = se; t2[tid] = sn;
    __syncthreads();
    if (tid < 64) {
        float e = 0.f, n = 0.f;
#pragma unroll
        for (int g = 0; g < 8; g++) { e += t1[g * 64 + tid]; n += t2[g * 64 + tid]; }
        ctx[tid]       = n * (1.f / (float)Nn);
        ctx[64 + tid]  = e * (1.f / (float)Ne);
        ctx[128 + tid] = g_zhist[tid];
    }
    __syncthreads();
    float p = 0.f;
    const int i0 = c * 24;
#pragma unroll
    for (int i = 0; i < 24; i++) p = fmaf(ctx[i0 + i], W1[(i0 + i) * 64 + j], p);
    __syncthreads();
    t1[tid] = p;
    __syncthreads();
    if (tid < 64) {
        float s = b1[tid];
#pragma unroll
        for (int g = 0; g < 8; g++) s += t1[g * 64 + tid];
        g_base[tid] = s;
        g_av[tid]   = W1[192 * 64 + tid];
        g_bv[tid]   = W1[193 * 64 + tid];
        g_w2v[tid]  = W2f[tid];
    }
}

// ---------------- kernel 3: candidate scoring (ILP=4, u64 shared wt) ------
__global__ void __launch_bounds__(256) k3(const int* __restrict__ cand, int P,
                                          const int* __restrict__ Np,
                                          const float* __restrict__ fb2,
                                          float* __restrict__ out)
{
    __shared__ __align__(16) u64 s4[128];   // [jp]{base2, a2, b2, w22}
    const int tid = threadIdx.x;
    if (tid < 32) {
        s4[tid * 4 + 0] = pk2(g_base[2 * tid], g_base[2 * tid + 1]);
        s4[tid * 4 + 1] = pk2(g_av[2 * tid],   g_av[2 * tid + 1]);
        s4[tid * 4 + 2] = pk2(g_bv[2 * tid],   g_bv[2 * tid + 1]);
        s4[tid * 4 + 3] = pk2(g_w2v[2 * tid],  g_w2v[2 * tid + 1]);
    }
    const float invd = 1.f / ((float)(*Np) - 1.f + 1e-9f);
    const float bias2 = fb2[0];
    __syncthreads();

    int p = blockIdx.x * 1024 + tid;
#pragma unroll
    for (int i = 0; i < 4; i++, p += 256) {
        if (p < P) {
            const int2 cp = ((const int2*)cand)[p];
            const float cx = (float)cp.x * invd;
            const float cy = (float)cp.y * invd;
            const u64 cx2 = pk2(cx, cx), cy2 = pk2(cy, cy);
            u64 acc0 = 0, acc1 = 0;
#pragma unroll
            for (int jp = 0; jp < 32; jp += 2) {
                {
                    u64 tt = f2fma(cx2, s4[jp * 4 + 1], s4[jp * 4 + 0]);
                    tt = f2fma(cy2, s4[jp * 4 + 2], tt);
                    float l, h; up2(tt, l, h);
                    u64 hh = pk2(fmaxf(l, 0.f), fmaxf(h, 0.f));
                    acc0 = f2fma(hh, s4[jp * 4 + 3], acc0);
                }
                {
                    u64 tt = f2fma(cx2, s4[(jp + 1) * 4 + 1], s4[(jp + 1) * 4 + 0]);
                    tt = f2fma(cy2, s4[(jp + 1) * 4 + 2], tt);
                    float l, h; up2(tt, l, h);
                    u64 hh = pk2(fmaxf(l, 0.f), fmaxf(h, 0.f));
                    acc1 = f2fma(hh, s4[(jp + 1) * 4 + 3], acc1);
                }
            }
            float r0, r1, r2, r3;
            up2(acc0, r0, r1); up2(acc1, r2, r3);
            out[p] = (r0 + r1) + (r2 + r3) + bias2;
        }
    }
}

// ---------------- launch ---------------------------------------------------
extern "C" void kernel_launch(void* const* d_in, const int* in_sizes, int n_in,
                              void* d_out, int out_size)
{
    const float* node  = (const float*)d_in[0];
    const float* edge  = (const float*)d_in[1];
    const float* hist  = (const float*)d_in[2];
    const int*   cand  = (const int*)d_in[3];
    const int*   Np    = (const int*)d_in[4];
    const float* nodeW = (const float*)d_in[5];
    const float* nodeb = (const float*)d_in[6];
    const float* edgeW = (const float*)d_in[7];
    const float* edgeb = (const float*)d_in[8];
    const float* Wih   = (const float*)d_in[9];
    const float* Whh   = (const float*)d_in[10];
    const float* bih   = (const float*)d_in[11];
    const float* bhh   = (const float*)d_in[12];
    const float* fW1   = (const float*)d_in[13];
    const float* fb1   = (const float*)d_in[14];
    const float* fW2   = (const float*)d_in[15];
    const float* fb2   = (const float*)d_in[16];

    const int Nn = in_sizes[0] / 2;
    const int Ne = in_sizes[1] / 5;
    const int T  = in_sizes[2] / 3;
    const int P  = in_sizes[3] / 2;

    const int GRID1 = 148;  // block 0 = LSTM, 147 = node/edge reduce (== NB)
    k1<<<GRID1, 512>>>(node, edge, hist, Nn, Ne, T,
                       nodeW, nodeb, edgeW, edgeb, Wih, Whh, bih, bhh);
    k2<<<1, 512>>>(Nn, Ne, fW1, fb1, fW2);
    const int g3 = (P + 1023) / 1024;
    k3<<<g3, 256>>>(cand, P, Np, fb2, (float*)d_out);
}